// round 1
// baseline (speedup 1.0000x reference)
#include <cuda_runtime.h>
#include <cuda_bf16.h>

// YOLO post-process:
//   in : (16, 25200, 85) f32 rows = [x, y, w, h, conf, cls0..cls79]
//   out: (16, 25200, 6)  f32 rows = [x-w/2, y-h/2, x+w/2, y+h/2, conf*max(cls), argmax(cls)]
//        zeroed where conf*max(cls) <= 0.25
//
// One warp per row. Lane l loads elements l, l+32, (l<21) l+64 — coalesced
// contiguous bursts. 80-class max/argmax via shfl_xor butterfly with
// first-index tie-break. Output staged through smem for one contiguous
// 192B store per block.

static constexpr int   ROWLEN          = 85;
static constexpr int   OUTLEN          = 6;
static constexpr int   WARPS_PER_BLOCK = 8;
static constexpr int   THREADS         = WARPS_PER_BLOCK * 32;
static constexpr float CONF_THRESH     = 0.25f;

__global__ __launch_bounds__(THREADS)
void yolo_post_kernel(const float* __restrict__ in,
                      float* __restrict__ out,
                      int nrows)
{
    __shared__ float s_out[WARPS_PER_BLOCK * OUTLEN];

    const int warp_in_block = threadIdx.x >> 5;
    const int lane          = threadIdx.x & 31;
    const int row           = blockIdx.x * WARPS_PER_BLOCK + warp_in_block;

    if (row < nrows) {
        const float* rp = in + (size_t)row * ROWLEN;

        // Coalesced row load: lanes cover [0,32), [32,64), [64,85)
        const float v0 = rp[lane];
        const float v1 = rp[lane + 32];
        const float v2 = (lane < 21) ? rp[lane + 64] : -1e30f;

        // Per-lane max/argmax over class elements (global indices 5..84,
        // class indices 0..79). Within a lane the candidate indices are
        // strictly increasing (l-5 < l+27 < l+59), so strict '>' keeps the
        // first-max semantics of jnp.argmax.
        float m;
        int   mi;
        if (lane >= 5) { m = v0;     mi = lane - 5; }
        else           { m = -1e30f; mi = 1 << 30;  }
        if (v1 > m) { m = v1; mi = lane + 27; }
        if (v2 > m) { m = v2; mi = lane + 59; }

        // Butterfly reduction: all lanes end with (max, first index).
        #pragma unroll
        for (int off = 16; off; off >>= 1) {
            const float om  = __shfl_xor_sync(0xffffffffu, m,  off);
            const int   omi = __shfl_xor_sync(0xffffffffu, mi, off);
            if (om > m || (om == m && omi < mi)) { m = om; mi = omi; }
        }

        // Broadcast box fields from lanes 0..4 (their v0).
        const float x    = __shfl_sync(0xffffffffu, v0, 0);
        const float y    = __shfl_sync(0xffffffffu, v0, 1);
        const float w    = __shfl_sync(0xffffffffu, v0, 2);
        const float h    = __shfl_sync(0xffffffffu, v0, 3);
        const float conf = __shfl_sync(0xffffffffu, v0, 4);

        const float score = conf * m;
        const bool  keep  = score > CONF_THRESH;

        float o = 0.0f;
        switch (lane) {
            case 0: o = x - 0.5f * w;  break;
            case 1: o = y - 0.5f * h;  break;
            case 2: o = x + 0.5f * w;  break;
            case 3: o = y + 0.5f * h;  break;
            case 4: o = score;         break;
            case 5: o = (float)mi;     break;
            default: break;
        }
        if (lane < OUTLEN)
            s_out[warp_in_block * OUTLEN + lane] = keep ? o : 0.0f;
    }
    __syncthreads();

    // Contiguous 192B store per block (8 rows x 6 floats).
    const int base_row = blockIdx.x * WARPS_PER_BLOCK;
    const int i        = threadIdx.x;
    if (i < WARPS_PER_BLOCK * OUTLEN) {
        const int r = base_row + i / OUTLEN;
        if (r < nrows)
            out[(size_t)base_row * OUTLEN + i] = s_out[i];
    }
}

extern "C" void kernel_launch(void* const* d_in, const int* in_sizes, int n_in,
                              void* d_out, int out_size)
{
    const float* in  = (const float*)d_in[0];
    float*       out = (float*)d_out;

    const int nrows  = out_size / OUTLEN;                       // 403200
    const int blocks = (nrows + WARPS_PER_BLOCK - 1) / WARPS_PER_BLOCK;

    yolo_post_kernel<<<blocks, THREADS>>>(in, out, nrows);
}

// round 2
// speedup vs baseline: 2.9289x; 2.9289x over previous
#include <cuda_runtime.h>
#include <cuda_bf16.h>

// YOLO post-process:
//   in : (16, 25200, 85) f32 rows = [x, y, w, h, conf, cls0..cls79]
//   out: (16, 25200, 6)  f32 rows = [x-w/2, y-h/2, x+w/2, y+h/2, conf*max(cls), argmax(cls)]
//        zeroed where conf*max(cls) <= 0.25
//
// R2: 4 threads per row (8 rows per warp). Lane sub-index j = lane&3 covers
// elements e = j + 4k, k = 0..21. Lane j's k=0 element is box field j
// (x,y,w,h); conf is lane0's k=1 element. Per-lane serial max/argmax over its
// ~21 class elements, then a 2-round shfl_xor butterfly across the 4-lane
// group with first-index tie-break. ~15 warp-instructions per row vs ~168 in
// the warp-per-row version (issue/ALU was the R1 bottleneck: alu=53.6%,
// issue=65.6%, DRAM only 20.3%).

static constexpr int   ROWLEN        = 85;
static constexpr int   OUTLEN        = 6;
static constexpr int   ROWS_PER_WARP = 8;
static constexpr int   THREADS       = 256;
static constexpr int   ROWS_PER_BLK  = (THREADS / 32) * ROWS_PER_WARP;  // 64
static constexpr float CONF_THRESH   = 0.25f;
static constexpr float NEG_INF       = -1e30f;

__global__ __launch_bounds__(THREADS)
void yolo_post_kernel(const float* __restrict__ in,
                      float* __restrict__ out,
                      int nrows)
{
    __shared__ float s_out[ROWS_PER_BLK * OUTLEN];   // 1536 B

    const int lane = threadIdx.x & 31;
    const int wid  = threadIdx.x >> 5;
    const int g    = lane >> 2;          // row subgroup within warp (0..7)
    const int j    = lane & 3;           // sub-lane within row group (0..3)

    const int rowloc = wid * ROWS_PER_WARP + g;            // 0..63
    const int row    = blockIdx.x * ROWS_PER_BLK + rowloc;

    if (row < nrows) {
        const float* rp = in + (size_t)row * ROWLEN;

        // Load elements e = j + 4k for k = 0..21. k=21 only valid for j==0
        // (e=84); other lanes would read past the row.
        float v[22];
        #pragma unroll
        for (int k = 0; k < 21; k++)
            v[k] = rp[j + 4 * k];
        v[21] = (j == 0) ? rp[84] : NEG_INF;

        // Box fields: lane j's v[0] is element j (x,y,w,h). conf = lane0 v[1].
        const float box = v[0];

        // Per-lane max/argmax over class elements (e>=5).
        // For j==0, k=1 is element 4 (conf) -> exclude.
        float m  = NEG_INF;
        int   mk = 1;
        #pragma unroll
        for (int k = 1; k < 22; k++) {
            float c = v[k];
            if (k == 1 && j == 0) c = NEG_INF;
            if (c > m) { m = c; mk = k; }
        }
        int ci = j + 4 * mk - 5;         // class index 0..79

        // Butterfly across the 4-lane group; (max, first index) semantics.
        #pragma unroll
        for (int off = 1; off <= 2; off <<= 1) {
            const float om = __shfl_xor_sync(0xffffffffu, m,  off);
            const int   oi = __shfl_xor_sync(0xffffffffu, ci, off);
            if (om > m || (om == m && oi < ci)) { m = om; ci = oi; }
        }

        // Distribute box fields within the group:
        //   a = x (j even) / y (j odd);  b = w (j even) / h (j odd)
        const int   base = lane & ~3;
        const float a    = __shfl_sync(0xffffffffu, box,  base + (j & 1));
        const float b    = __shfl_sync(0xffffffffu, box,  base + 2 + (j & 1));
        const float conf = __shfl_sync(0xffffffffu, v[1], base);

        const float score = conf * m;
        const bool  keep  = score > CONF_THRESH;

        // o_j: j=0: x-w/2, j=1: y-h/2, j=2: x+w/2, j=3: y+h/2
        const float sign = (j < 2) ? -0.5f : 0.5f;
        const float o    = fmaf(sign, b, a);

        float* srow = &s_out[rowloc * OUTLEN];
        srow[j] = keep ? o : 0.0f;
        if (j == 0) srow[4] = keep ? score : 0.0f;
        if (j == 1) srow[5] = keep ? (float)ci : 0.0f;
    }
    __syncthreads();

    // Contiguous 1536B store per block (64 rows x 6 floats).
    const size_t obase = (size_t)blockIdx.x * (ROWS_PER_BLK * OUTLEN);
    const int    nvals = ROWS_PER_BLK * OUTLEN;                 // 384
    const size_t olim  = (size_t)nrows * OUTLEN;
    #pragma unroll
    for (int i = threadIdx.x; i < nvals; i += THREADS) {
        if (obase + i < olim)
            out[obase + i] = s_out[i];
    }
}

extern "C" void kernel_launch(void* const* d_in, const int* in_sizes, int n_in,
                              void* d_out, int out_size)
{
    const float* in  = (const float*)d_in[0];
    float*       out = (float*)d_out;

    const int nrows  = out_size / OUTLEN;                        // 403200
    const int blocks = (nrows + ROWS_PER_BLK - 1) / ROWS_PER_BLK; // 6300

    yolo_post_kernel<<<blocks, THREADS>>>(in, out, nrows);
}